// round 8
// baseline (speedup 1.0000x reference)
#include <cuda_runtime.h>
#include <cstdint>

// KV-cache scatter-copy, pure HBM streaming.
//   L=8, B=2, H=8, S_FULL=4096, S_NEW=4, D=128, fp32
// out (2,L,B,H,S_FULL,D) = stack(past_k, past_v) with a 4-row window per
// (l,b,h) overwritten from new_k/new_v at target_positions[b].
//
// R8: persistent grid-stride variant of the R3 winner. grid = 148 SMs x 4
// CTAs = 592 resident blocks, each looping over ~28 tiles -> eliminates the
// ~27 wave transitions whose drain/refill gaps plausibly account for the
// 14.5% DRAM-idle fraction. Per-tile body identical to R3: 8x float4
// front-batched loads, .cs load/store policy, block-uniform decode.

static constexpr unsigned D4       = 32;                       // float4 per row
static constexpr unsigned S_FULL   = 4096;
static constexpr unsigned S_NEW    = 4;
static constexpr unsigned H        = 8;
static constexpr unsigned B        = 2;
static constexpr unsigned L        = 8;
static constexpr unsigned PAST_F4  = L * B * H * S_FULL * D4;  // 2^24
static constexpr unsigned TOTAL_F4 = 2u * PAST_F4;             // 2^25

static constexpr unsigned TPB    = 256;
static constexpr unsigned U      = 8;
static constexpr unsigned TILE   = TPB * U;                    // 2048 float4 per tile
static constexpr unsigned NTILES = TOTAL_F4 / TILE;            // 16384
static constexpr unsigned GRID   = 148 * 4;                    // 592 resident CTAs

__global__ void __launch_bounds__(TPB) kv_scatter_copy_persist(
    const float4* __restrict__ pk,
    const float4* __restrict__ pv,
    const float4* __restrict__ nk,
    const float4* __restrict__ nv,
    const int*    __restrict__ tpos,
    float4*       __restrict__ out)
{
    for (unsigned t = blockIdx.x; t < NTILES; t += GRID) {
        const unsigned base = t * TILE + threadIdx.x;

        // Bits >= 17 (h|b|l|kv) are uniform across this tile (TILE = 2^11).
        const unsigned r  = base >> 17;
        const unsigned h  = r & (H - 1);
        const unsigned b  = (r >> 3) & (B - 1);
        const unsigned l  = (r >> 4) & (L - 1);
        const unsigned kv = r >> 7;

        const unsigned off = (unsigned)__ldg(&tpos[b]);

        const float4* __restrict__ past = kv ? pv : pk;   // same layout as out slab
        const float4* __restrict__ nw   = (kv ? nv : nk)
                                          + (((l * B + b) * H + h) * S_NEW) * D4;

        float4 v[U];
#pragma unroll
        for (unsigned u = 0; u < U; u++) {
            const unsigned i  = base + u * TPB;
            const unsigned s  = (i >> 5) & (S_FULL - 1);
            const unsigned d4 = i & (D4 - 1);
            const unsigned w  = s - off;                  // in-window iff < S_NEW
            if (w < S_NEW) {
                v[u] = __ldg(nw + w * D4 + d4);           // tiny window: keep cached
            } else {
                v[u] = __ldcs(past + (i & (PAST_F4 - 1)));// read-once bulk: streaming
            }
        }
#pragma unroll
        for (unsigned u = 0; u < U; u++) {
            __stcs(&out[base + u * TPB], v[u]);           // streaming store
        }
    }
}

extern "C" void kernel_launch(void* const* d_in, const int* in_sizes, int n_in,
                              void* d_out, int out_size)
{
    const float4* pk = (const float4*)d_in[0];
    const float4* pv = (const float4*)d_in[1];
    const float4* nk = (const float4*)d_in[2];
    const float4* nv = (const float4*)d_in[3];
    const int*    tp = (const int*)d_in[4];
    float4*       out = (float4*)d_out;

    kv_scatter_copy_persist<<<GRID, TPB>>>(pk, pv, nk, nv, tp, out);
}

// round 9
// speedup vs baseline: 1.1126x; 1.1126x over previous
#include <cuda_runtime.h>
#include <cstdint>

// KV-cache scatter-copy, pure HBM streaming.
//   L=8, B=2, H=8, S_FULL=4096, S_NEW=4, D=128, fp32
// out (2,L,B,H,S_FULL,D) = stack(past_k, past_v) with a 4-row window per
// (l,b,h) overwritten from new_k/new_v at target_positions[b].
//
// R9: split-batch variant of the R3 winner. 8x float4 per thread processed
// as two rounds of (4 front-batched loads -> 4 stores): only 4 float4 live
// at once -> ~36-40 regs -> higher occupancy (more resident warps) while
// keeping warp-level MLP=4 per round. Goal: combine R2's occupancy with
// R3's per-thread throughput.

static constexpr unsigned D4       = 32;                       // float4 per row
static constexpr unsigned S_FULL   = 4096;
static constexpr unsigned S_NEW    = 4;
static constexpr unsigned H        = 8;
static constexpr unsigned B        = 2;
static constexpr unsigned L        = 8;
static constexpr unsigned PAST_F4  = L * B * H * S_FULL * D4;  // 2^24
static constexpr unsigned TOTAL_F4 = 2u * PAST_F4;             // 2^25

static constexpr unsigned TPB  = 256;
static constexpr unsigned UB   = 4;                            // loads per batch
static constexpr unsigned NB   = 2;                            // batches
static constexpr unsigned TILE = TPB * UB * NB;                // 2048 float4 per block

__global__ void __launch_bounds__(TPB) kv_scatter_copy_r9(
    const float4* __restrict__ pk,
    const float4* __restrict__ pv,
    const float4* __restrict__ nk,
    const float4* __restrict__ nv,
    const int*    __restrict__ tpos,
    float4*       __restrict__ out)
{
    const unsigned base0 = blockIdx.x * TILE + threadIdx.x;

    // Bits >= 17 (h|b|l|kv) are uniform across the whole block (TILE = 2^11).
    const unsigned r  = base0 >> 17;
    const unsigned h  = r & (H - 1);
    const unsigned b  = (r >> 3) & (B - 1);
    const unsigned l  = (r >> 4) & (L - 1);
    const unsigned kv = r >> 7;

    const unsigned off = (unsigned)__ldg(&tpos[b]);

    const float4* __restrict__ past = kv ? pv : pk;     // same layout as out slab
    const float4* __restrict__ nw   = (kv ? nv : nk)
                                      + (((l * B + b) * H + h) * S_NEW) * D4;

#pragma unroll
    for (unsigned nb = 0; nb < NB; nb++) {
        const unsigned base = base0 + nb * (TPB * UB);
        float4 v[UB];
#pragma unroll
        for (unsigned u = 0; u < UB; u++) {
            const unsigned i  = base + u * TPB;
            const unsigned s  = (i >> 5) & (S_FULL - 1);
            const unsigned d4 = i & (D4 - 1);
            const unsigned w  = s - off;                // in-window iff < S_NEW
            if (w < S_NEW) {
                v[u] = __ldg(nw + w * D4 + d4);         // tiny window: keep cached
            } else {
                v[u] = __ldcs(past + (i & (PAST_F4 - 1)));  // read-once: streaming
            }
        }
#pragma unroll
        for (unsigned u = 0; u < UB; u++) {
            __stcs(&out[base + u * TPB], v[u]);         // streaming store
        }
    }
}

extern "C" void kernel_launch(void* const* d_in, const int* in_sizes, int n_in,
                              void* d_out, int out_size)
{
    const float4* pk = (const float4*)d_in[0];
    const float4* pv = (const float4*)d_in[1];
    const float4* nk = (const float4*)d_in[2];
    const float4* nv = (const float4*)d_in[3];
    const int*    tp = (const int*)d_in[4];
    float4*       out = (float4*)d_out;

    constexpr unsigned blocks = TOTAL_F4 / TILE;        // 16384
    kv_scatter_copy_r9<<<blocks, TPB>>>(pk, pv, nk, nv, tp, out);
}

// round 10
// speedup vs baseline: 1.1178x; 1.0047x over previous
#include <cuda_runtime.h>
#include <cstdint>

// FINAL (session answer): KV-cache scatter-copy, pure HBM streaming at the
// read/write-turnaround wall.
//
// Evidence for the wall: eight configurations (MLP 1/4/8, split-batch,
// 128/256-bit LDG/STG, occ 50-83%, tile 16-64KB, cache policies, CE memcpy,
// persistent grid) all land at 150-152us kernel / 84.5-85.7% DRAM
// (6.7-6.8 TB/s). Traffic is at the information floor (512MB R + 512MB W,
// single fused pass). Remaining 14% of spec is DRAM-side turnaround, not
// reachable from the SM.
//
//   L=8, B=2, H=8, S_FULL=4096, S_NEW=4, D=128, fp32
// out (2,L,B,H,S_FULL,D) = stack(past_k, past_v) with a 4-row window per
// (l,b,h) overwritten from new_k/new_v at target_positions[b].
//
// Best variant (R3): 8x float4 per thread, front-batched loads (MLP_p1=8),
// .cs loads on read-once past data, .cs stores, block-uniform kv/l/b/h
// decode (tile = 2^11 float4 < 2^17 boundary -> bits >=17 uniform per block).

static constexpr unsigned D4       = 32;                       // float4 per row
static constexpr unsigned S_FULL   = 4096;
static constexpr unsigned S_NEW    = 4;
static constexpr unsigned H        = 8;
static constexpr unsigned B        = 2;
static constexpr unsigned L        = 8;
static constexpr unsigned PAST_F4  = L * B * H * S_FULL * D4;  // 2^24
static constexpr unsigned TOTAL_F4 = 2u * PAST_F4;             // 2^25

static constexpr unsigned TPB  = 256;
static constexpr unsigned U    = 8;
static constexpr unsigned TILE = TPB * U;                      // 2048 float4 per block

__global__ void __launch_bounds__(TPB) kv_scatter_copy_final(
    const float4* __restrict__ pk,
    const float4* __restrict__ pv,
    const float4* __restrict__ nk,
    const float4* __restrict__ nv,
    const int*    __restrict__ tpos,
    float4*       __restrict__ out)
{
    const unsigned base = blockIdx.x * TILE + threadIdx.x;

    // Bits >= 17 (h|b|l|kv) are uniform across the whole block.
    const unsigned r  = base >> 17;
    const unsigned h  = r & (H - 1);
    const unsigned b  = (r >> 3) & (B - 1);
    const unsigned l  = (r >> 4) & (L - 1);
    const unsigned kv = r >> 7;

    const unsigned off = (unsigned)__ldg(&tpos[b]);

    const float4* __restrict__ past = kv ? pv : pk;     // same layout as out slab
    const float4* __restrict__ nw   = (kv ? nv : nk)
                                      + (((l * B + b) * H + h) * S_NEW) * D4;

    float4 v[U];
#pragma unroll
    for (unsigned u = 0; u < U; u++) {
        const unsigned i  = base + u * TPB;
        const unsigned s  = (i >> 5) & (S_FULL - 1);
        const unsigned d4 = i & (D4 - 1);
        const unsigned w  = s - off;                    // in-window iff < S_NEW (unsigned wrap)
        if (w < S_NEW) {
            v[u] = __ldg(nw + w * D4 + d4);             // tiny window: keep in L2
        } else {
            v[u] = __ldcs(past + (i & (PAST_F4 - 1)));  // read-once bulk: streaming
        }
    }
#pragma unroll
    for (unsigned u = 0; u < U; u++) {
        __stcs(&out[base + u * TPB], v[u]);             // streaming store
    }
}

extern "C" void kernel_launch(void* const* d_in, const int* in_sizes, int n_in,
                              void* d_out, int out_size)
{
    const float4* pk = (const float4*)d_in[0];
    const float4* pv = (const float4*)d_in[1];
    const float4* nk = (const float4*)d_in[2];
    const float4* nv = (const float4*)d_in[3];
    const int*    tp = (const int*)d_in[4];
    float4*       out = (float4*)d_out;

    constexpr unsigned blocks = TOTAL_F4 / TILE;        // 16384
    kv_scatter_copy_final<<<blocks, TPB>>>(pk, pv, nk, nv, tp, out);
}

// round 11
// speedup vs baseline: 1.1281x; 1.0092x over previous
#include <cuda_runtime.h>
#include <cstdint>

// KV-cache scatter-copy, pure HBM streaming.
//   L=8, B=2, H=8, S_FULL=4096, S_NEW=4, D=128, fp32
// out (2,L,B,H,S_FULL,D) = stack(past_k, past_v) with a 4-row window per
// (l,b,h) overwritten from new_k/new_v at target_positions[b].
//
// R11 (last probe): TPB=128, U=8 -> 6K regs/CTA -> up to 10 CTAs/SM.
// The only unvisited corner of the (MLP x occupancy) grid: per-warp MLP=8
// AND occ ~75-100% simultaneously (R3 had MLP=8/occ=50, R2 MLP=4/occ=83).
// SM-wide outstanding loads ~1.5-2x any prior config.

static constexpr unsigned D4       = 32;                       // float4 per row
static constexpr unsigned S_FULL   = 4096;
static constexpr unsigned S_NEW    = 4;
static constexpr unsigned H        = 8;
static constexpr unsigned B        = 2;
static constexpr unsigned L        = 8;
static constexpr unsigned PAST_F4  = L * B * H * S_FULL * D4;  // 2^24
static constexpr unsigned TOTAL_F4 = 2u * PAST_F4;             // 2^25

static constexpr unsigned TPB  = 128;
static constexpr unsigned U    = 8;
static constexpr unsigned TILE = TPB * U;                      // 1024 float4 per block

__global__ void __launch_bounds__(TPB) kv_scatter_copy_r11(
    const float4* __restrict__ pk,
    const float4* __restrict__ pv,
    const float4* __restrict__ nk,
    const float4* __restrict__ nv,
    const int*    __restrict__ tpos,
    float4*       __restrict__ out)
{
    const unsigned base = blockIdx.x * TILE + threadIdx.x;

    // Bits >= 17 (h|b|l|kv) are uniform across the whole block (TILE = 2^10).
    const unsigned r  = base >> 17;
    const unsigned h  = r & (H - 1);
    const unsigned b  = (r >> 3) & (B - 1);
    const unsigned l  = (r >> 4) & (L - 1);
    const unsigned kv = r >> 7;

    const unsigned off = (unsigned)__ldg(&tpos[b]);

    const float4* __restrict__ past = kv ? pv : pk;     // same layout as out slab
    const float4* __restrict__ nw   = (kv ? nv : nk)
                                      + (((l * B + b) * H + h) * S_NEW) * D4;

    float4 v[U];
#pragma unroll
    for (unsigned u = 0; u < U; u++) {
        const unsigned i  = base + u * TPB;
        const unsigned s  = (i >> 5) & (S_FULL - 1);
        const unsigned d4 = i & (D4 - 1);
        const unsigned w  = s - off;                    // in-window iff < S_NEW (unsigned wrap)
        if (w < S_NEW) {
            v[u] = __ldg(nw + w * D4 + d4);             // tiny window: keep in L2
        } else {
            v[u] = __ldcs(past + (i & (PAST_F4 - 1)));  // read-once bulk: streaming
        }
    }
#pragma unroll
    for (unsigned u = 0; u < U; u++) {
        __stcs(&out[base + u * TPB], v[u]);             // streaming store
    }
}

extern "C" void kernel_launch(void* const* d_in, const int* in_sizes, int n_in,
                              void* d_out, int out_size)
{
    const float4* pk = (const float4*)d_in[0];
    const float4* pv = (const float4*)d_in[1];
    const float4* nk = (const float4*)d_in[2];
    const float4* nv = (const float4*)d_in[3];
    const int*    tp = (const int*)d_in[4];
    float4*       out = (float4*)d_out;

    constexpr unsigned blocks = TOTAL_F4 / TILE;        // 32768
    kv_scatter_copy_r11<<<blocks, TPB>>>(pk, pv, nk, nv, tp, out);
}